// round 12
// baseline (speedup 1.0000x reference)
#include <cuda_runtime.h>
#include <cstdint>

// 4 partial projection buffers: [z*2+ks][512*512]
// 0: lig K[0:256), 1: lig K[256:512), 2: rec K[0:256) (+bias), 3: rec K[256:512)
__device__ float g_parts[4][512 * 512];

#define D 512
#define BM 64
#define BN 64
#define BK 32
#define KSPLIT 256
#define NKT (KSPLIT / BK)   // 8
#define JBLK 64

__device__ __forceinline__ uint32_t f2tf32(float x) {
    uint32_t r;
    asm("cvt.rna.tf32.f32 %0, %1;" : "=r"(r) : "f"(x));
    return r;
}

__device__ __forceinline__ void mma_tf32(float* d, const uint32_t* a, const uint32_t* b) {
    asm volatile(
        "mma.sync.aligned.m16n8k8.row.col.f32.tf32.tf32.f32 "
        "{%0,%1,%2,%3}, {%4,%5,%6,%7}, {%8,%9}, {%0,%1,%2,%3};"
        : "+f"(d[0]), "+f"(d[1]), "+f"(d[2]), "+f"(d[3])
        : "r"(a[0]), "r"(a[1]), "r"(a[2]), "r"(a[3]), "r"(b[0]), "r"(b[1]));
}

// Partial C[i,o] = sum_{k in chunk} A[i,k] * W[o, w_off + k]  (+ bias on z=1,ks=0).
// Split-K=2: grid (8,8,4) = 256 blocks, 8 K-iterations each.
__global__ __launch_bounds__(256) void proj_gemm_kernel(
    const float* __restrict__ lig,
    const float* __restrict__ rec,
    const float* __restrict__ W,
    const float* __restrict__ bias)
{
    __shared__ uint32_t SaHi[BM * BK];
    __shared__ uint32_t SaLo[BM * BK];
    __shared__ uint32_t SbHi[BN * BK];
    __shared__ uint32_t SbLo[BN * BK];

    const int bz = blockIdx.z;      // 0..3
    const int z  = bz >> 1;         // 0 = ligand, 1 = receptor
    const int ks = bz & 1;          // K chunk
    const float* A = (z == 0) ? lig : rec;
    float* C = g_parts[bz];
    // float4 offset of this chunk within a row of A / within W's half-row
    const int a_off4 = ks * (KSPLIT / 4);
    const int w_off4 = ((z == 0) ? 0 : (D / 4)) + a_off4;

    const int tid = threadIdx.x;
    const int lane = tid & 31;
    const int wid = tid >> 5;
    const int mwarp = wid >> 2;     // 0..1
    const int nwarp = wid & 3;      // 0..3
    const int i0 = blockIdx.y * BM;
    const int o0 = blockIdx.x * BN;

    const int lr0 = tid >> 3;       // 0..31
    const int lc  = tid & 7;        // float4 col 0..7
    const float4* A4 = reinterpret_cast<const float4*>(A);
    const float4* W4 = reinterpret_cast<const float4*>(W);

    float acc[2][2][4] = {};

    auto scatA = [&](int r, float4 v) {
        #pragma unroll
        for (int q = 0; q < 4; q++) {
            float val = (q == 0) ? v.x : (q == 1) ? v.y : (q == 2) ? v.z : v.w;
            int kl = lc * 4 + q;
            int mtile = r >> 4, ktile = kl >> 3;
            int rr = r & 15, cc = kl & 7;
            int ln = ((rr & 7) << 2) | (cc & 3);
            int idx = ((cc & 4) >> 1) | ((rr & 8) >> 3);
            int off = ((mtile * 4 + ktile) * 32 + ln) * 4 + idx;
            uint32_t hi = f2tf32(val);
            SaHi[off] = hi;
            SaLo[off] = f2tf32(val - __uint_as_float(hi));
        }
    };
    auto scatB = [&](int r, float4 v) {
        #pragma unroll
        for (int q = 0; q < 4; q++) {
            float val = (q == 0) ? v.x : (q == 1) ? v.y : (q == 2) ? v.z : v.w;
            int kl = lc * 4 + q;
            int ntile = r >> 3, ktile = kl >> 3;
            int n = r & 7, cc = kl & 7;
            int ln = (n << 2) | (cc & 3);
            int idx = (cc & 4) >> 2;
            int off = ((ntile * 4 + ktile) * 32 + ln) * 2 + idx;
            uint32_t hi = f2tf32(val);
            SbHi[off] = hi;
            SbLo[off] = f2tf32(val - __uint_as_float(hi));
        }
    };

    {
        float4 va0 = A4[(size_t)(i0 + lr0)      * (D / 4) + a_off4 + lc];
        float4 va1 = A4[(size_t)(i0 + lr0 + 32) * (D / 4) + a_off4 + lc];
        float4 vb0 = W4[(size_t)(o0 + lr0)      * (2 * D / 4) + w_off4 + lc];
        float4 vb1 = W4[(size_t)(o0 + lr0 + 32) * (2 * D / 4) + w_off4 + lc];
        scatA(lr0, va0); scatA(lr0 + 32, va1);
        scatB(lr0, vb0); scatB(lr0 + 32, vb1);
    }
    __syncthreads();

    for (int t = 0; t < NKT; t++) {
        float4 va0, va1, vb0, vb1;
        if (t + 1 < NKT) {
            const int kc4 = (t + 1) * (BK / 4);
            va0 = A4[(size_t)(i0 + lr0)      * (D / 4) + a_off4 + kc4 + lc];
            va1 = A4[(size_t)(i0 + lr0 + 32) * (D / 4) + a_off4 + kc4 + lc];
            vb0 = W4[(size_t)(o0 + lr0)      * (2 * D / 4) + w_off4 + kc4 + lc];
            vb1 = W4[(size_t)(o0 + lr0 + 32) * (2 * D / 4) + w_off4 + kc4 + lc];
        }

        #pragma unroll
        for (int k8 = 0; k8 < 4; k8++) {
            uint32_t ahi[2][4], alo[2][4], bhi[2][2], blo[2][2];
            #pragma unroll
            for (int mt = 0; mt < 2; mt++) {
                int base = (((mwarp * 2 + mt) * 4 + k8) * 32 + lane) * 4;
                *reinterpret_cast<uint4*>(ahi[mt]) = *reinterpret_cast<const uint4*>(&SaHi[base]);
                *reinterpret_cast<uint4*>(alo[mt]) = *reinterpret_cast<const uint4*>(&SaLo[base]);
            }
            #pragma unroll
            for (int nt = 0; nt < 2; nt++) {
                int base = (((nwarp * 2 + nt) * 4 + k8) * 32 + lane) * 2;
                *reinterpret_cast<uint2*>(bhi[nt]) = *reinterpret_cast<const uint2*>(&SbHi[base]);
                *reinterpret_cast<uint2*>(blo[nt]) = *reinterpret_cast<const uint2*>(&SbLo[base]);
            }
            #pragma unroll
            for (int mt = 0; mt < 2; mt++)
                #pragma unroll
                for (int nt = 0; nt < 2; nt++) {
                    mma_tf32(acc[mt][nt], ahi[mt], bhi[nt]);
                    mma_tf32(acc[mt][nt], alo[mt], bhi[nt]);
                    mma_tf32(acc[mt][nt], ahi[mt], blo[nt]);
                }
        }

        __syncthreads();
        if (t + 1 < NKT) {
            scatA(lr0, va0); scatA(lr0 + 32, va1);
            scatB(lr0, vb0); scatB(lr0 + 32, vb1);
            __syncthreads();
        }
    }

    const bool add_bias = (z == 1) && (ks == 0);
    #pragma unroll
    for (int mt = 0; mt < 2; mt++) {
        #pragma unroll
        for (int nt = 0; nt < 2; nt++) {
            int row = i0 + mwarp * 32 + mt * 16 + (lane >> 2);
            int col = o0 + nwarp * 16 + nt * 8 + 2 * (lane & 3);
            float bv0 = 0.f, bv1 = 0.f;
            if (add_bias) { bv0 = bias[col]; bv1 = bias[col + 1]; }
            float2 lo_pair = make_float2(acc[mt][nt][0] + bv0, acc[mt][nt][1] + bv1);
            float2 hi_pair = make_float2(acc[mt][nt][2] + bv0, acc[mt][nt][3] + bv1);
            *reinterpret_cast<float2*>(&C[(size_t)row * D + col]) = lo_pair;
            *reinterpret_cast<float2*>(&C[(size_t)(row + 8) * D + col]) = hi_pair;
        }
    }

#if __CUDA_ARCH__ >= 900
    cudaTriggerProgrammaticLaunchCompletion();
#endif
}

// out[i, j, :] = (l0[i]+l1[i]) + (r0[j]+r1[j])   — partials combined in fixed order.
// Block = (1 i, 64 j), 128 threads, 4096 blocks (best measured config). PDL consumer.
__global__ __launch_bounds__(128) void pair_add_kernel(float4* __restrict__ out)
{
    const int c = threadIdx.x;            // float4 column 0..127
    const int i = blockIdx.y;
    const int j0 = blockIdx.x * JBLK;

    const float4* l0 = reinterpret_cast<const float4*>(g_parts[0]);
    const float4* l1 = reinterpret_cast<const float4*>(g_parts[1]);
    const float4* r0 = reinterpret_cast<const float4*>(g_parts[2]);
    const float4* r1 = reinterpret_cast<const float4*>(g_parts[3]);

    const float4* ap0 = l0 + i * 128 + c;
    const float4* ap1 = l1 + i * 128 + c;
    const float4* rp0 = r0 + (size_t)j0 * 128 + c;
    const float4* rp1 = r1 + (size_t)j0 * 128 + c;
    float4* op = out + ((size_t)i * D + j0) * 128 + c;

#if __CUDA_ARCH__ >= 900
    cudaGridDependencySynchronize();
#endif

    float4 a0 = *ap0, a1 = *ap1;
    float4 a;
    a.x = a0.x + a1.x; a.y = a0.y + a1.y;
    a.z = a0.z + a1.z; a.w = a0.w + a1.w;

    #pragma unroll 8
    for (int jj = 0; jj < JBLK; jj++) {
        float4 u = __ldg(rp0 + (size_t)jj * 128);
        float4 v = __ldg(rp1 + (size_t)jj * 128);
        float4 o;
        o.x = a.x + (u.x + v.x);
        o.y = a.y + (u.y + v.y);
        o.z = a.z + (u.z + v.z);
        o.w = a.w + (u.w + v.w);
        __stcs(op + (size_t)jj * 128, o);
    }
}

extern "C" void kernel_launch(void* const* d_in, const int* in_sizes, int n_in,
                              void* d_out, int out_size)
{
    const float* lig = (const float*)d_in[0];   // (512, 512)
    const float* rec = (const float*)d_in[1];   // (512, 512)
    const float* W   = (const float*)d_in[2];   // (512, 1024)
    const float* b   = (const float*)d_in[3];   // (512,)
    float* out = (float*)d_out;                 // (512, 512, 512)

    dim3 ggrd(D / BN, D / BM, 4);   // 8 x 8 x 4 = 256 blocks (split-K=2)
    proj_gemm_kernel<<<ggrd, 256>>>(lig, rec, W, b);

    cudaLaunchConfig_t cfg = {};
    cfg.gridDim = dim3(D / JBLK, D, 1);   // 8 x 512 = 4096 blocks
    cfg.blockDim = dim3(128, 1, 1);
    cfg.dynamicSmemBytes = 0;
    cfg.stream = 0;
    cudaLaunchAttribute attrs[1];
    attrs[0].id = cudaLaunchAttributeProgrammaticStreamSerialization;
    attrs[0].val.programmaticStreamSerializationAllowed = 1;
    cfg.attrs = attrs;
    cfg.numAttrs = 1;
    cudaLaunchKernelEx(&cfg, pair_add_kernel, reinterpret_cast<float4*>(out));
}